// round 5
// baseline (speedup 1.0000x reference)
#include <cuda_runtime.h>
#include <cuda_bf16.h>
#include <cstdint>

#define NN 4096
#define DD 64

// Scratch (device globals — no allocation allowed)
__device__ float g_cost[(size_t)NN * NN];          // 64 MB, fits L2
__device__ float g_x2[NN];
__device__ float g_y2[NN];
__device__ unsigned long long g_rowmin[NN];        // key = (cost_bits<<32) | col

__device__ __forceinline__ unsigned long long umin64(unsigned long long a, unsigned long long b) {
    return a < b ? a : b;
}

// -------------------------------------------------------------------------
// Kernel 1: squared norms. Lane l takes pair (2l, 2l+1): unfused muls, RN
// add, then shfl_down butterfly. (Empirically the exact order is irrelevant:
// ulp-scale perturbations do not flip the matching.)
// Also pre-fills out with identity AS FLOAT (liveness diagnostic).
// -------------------------------------------------------------------------
__global__ void norms_kernel(const float* __restrict__ x, const float* __restrict__ y,
                             float* __restrict__ out) {
    int gt = blockIdx.x * blockDim.x + threadIdx.x;
    if (gt < NN) out[gt] = (float)gt;

    int w = gt >> 5;           // global warp = row
    int lane = gt & 31;
    if (w >= NN) return;

    float2 xv = ((const float2*)(x + w * DD))[lane];
    float p = __fadd_rn(__fmul_rn(xv.x, xv.x), __fmul_rn(xv.y, xv.y));
    #pragma unroll
    for (int o = 16; o; o >>= 1)
        p = __fadd_rn(p, __shfl_down_sync(0xFFFFFFFFu, p, o));
    if (lane == 0) g_x2[w] = p;

    float2 yv = ((const float2*)(y + w * DD))[lane];
    p = __fadd_rn(__fmul_rn(yv.x, yv.x), __fmul_rn(yv.y, yv.y));
    #pragma unroll
    for (int o = 16; o; o >>= 1)
        p = __fadd_rn(p, __shfl_down_sync(0xFFFFFFFFu, p, o));
    if (lane == 0) g_y2[w] = p;
}

// -------------------------------------------------------------------------
// Kernel 2: cost matrix + fused per-row argmin (tie-break smallest col).
// EXACT fp32: dot = sequential ascending-k FFMA chain (sgemm order; within
// 1-2 ulp of any reasonable reference order, which is below the flip
// threshold established empirically in rounds 3-4).
// cost = sqrt(max((x2+y2) - 2*dot, 0)) with explicitly-rounded intrinsics.
// -------------------------------------------------------------------------
__global__ void cost_kernel(const float* __restrict__ x, const float* __restrict__ y) {
    __shared__ float xs[16 * DD];
    __shared__ float x2s[16];
    __shared__ unsigned long long minkey[16];

    int i0 = blockIdx.x * 16;
    int tid = threadIdx.x;

    for (int k = tid; k < 16 * DD; k += 256)
        xs[k] = x[(size_t)i0 * DD + k];
    if (tid < 16) {
        x2s[tid] = g_x2[i0 + tid];
        minkey[tid] = ~0ull;
    }
    __syncthreads();

    unsigned long long lk[16];
    #pragma unroll
    for (int r = 0; r < 16; r++) lk[r] = ~0ull;

    for (int jt = 0; jt < 16; jt++) {
        int j = jt * 256 + tid;
        const float4* yr = (const float4*)(y + (size_t)j * DD);
        float4 yv[16];
        #pragma unroll
        for (int q = 0; q < 16; q++) yv[q] = yr[q];
        float y2 = g_y2[j];

        #pragma unroll
        for (int r = 0; r < 16; r++) {
            float acc = 0.0f;
            #pragma unroll
            for (int q = 0; q < 16; q++) {
                acc = __fmaf_rn(xs[r * DD + q * 4 + 0], yv[q].x, acc);
                acc = __fmaf_rn(xs[r * DD + q * 4 + 1], yv[q].y, acc);
                acc = __fmaf_rn(xs[r * DD + q * 4 + 2], yv[q].z, acc);
                acc = __fmaf_rn(xs[r * DD + q * 4 + 3], yv[q].w, acc);
            }
            float ssum = __fadd_rn(x2s[r], y2);
            float u    = __fsub_rn(ssum, __fmul_rn(2.0f, acc));
            float sq   = fmaxf(u, 0.0f);
            float c    = __fsqrt_rn(sq);
            g_cost[(size_t)(i0 + r) * NN + j] = c;
            unsigned long long key =
                ((unsigned long long)__float_as_uint(c) << 32) | (unsigned)j;
            lk[r] = umin64(lk[r], key);
        }
    }
    #pragma unroll
    for (int r = 0; r < 16; r++) atomicMin(&minkey[r], lk[r]);
    __syncthreads();
    if (tid < 16) g_rowmin[i0 + tid] = minkey[tid];
}

// -------------------------------------------------------------------------
// Kernel 3: single-block persistent greedy (exactly equivalent to the
// reference's sorted-stable greedy: repeatedly take min (cost, i*n+j)
// feasible edge). Row minima cached in shared; invalidate-on-column-take.
// OUTPUT IS WRITTEN AS FLOAT32 (match index as a float value).
// -------------------------------------------------------------------------
__global__ __launch_bounds__(1024, 1)
void greedy_kernel(float* __restrict__ out) {
    __shared__ float          sval[NN];          // 16 KB   cached row min value (+inf = matched)
    __shared__ unsigned short scol[NN];          //  8 KB   cached row min column
    __shared__ unsigned short slist[NN];         //  8 KB   rows needing rescan
    __shared__ unsigned int   colfree[NN / 32];  // 512 B   free-column bitmap
    __shared__ unsigned long long wbest[32];
    __shared__ int cnt;
    __shared__ int pick_j;

    const float INF = __int_as_float(0x7f800000);
    int tid = threadIdx.x;
    int lane = tid & 31;
    int w = tid >> 5;

    for (int r = tid; r < NN; r += 1024) {
        unsigned long long k = g_rowmin[r];
        sval[r] = __uint_as_float((unsigned)(k >> 32));
        scol[r] = (unsigned short)(k & 0xFFFFu);
    }
    for (int c = tid; c < NN / 32; c += 1024) colfree[c] = 0xFFFFFFFFu;
    __syncthreads();

    for (int it = 0; it < NN; it++) {
        // ---- phase 1: argmin over cached row minima, tie-break smallest row
        unsigned long long bk = ~0ull;
        #pragma unroll
        for (int q = 0; q < 4; q++) {
            int r = tid + q * 1024;
            unsigned long long k =
                ((unsigned long long)__float_as_uint(sval[r]) << 32) | (unsigned)r;
            bk = umin64(bk, k);
        }
        #pragma unroll
        for (int o = 16; o; o >>= 1)
            bk = umin64(bk, __shfl_down_sync(0xFFFFFFFFu, bk, o));
        if (lane == 0) wbest[w] = bk;
        __syncthreads();
        if (w == 0) {
            unsigned long long k = wbest[lane];
            #pragma unroll
            for (int o = 16; o; o >>= 1)
                k = umin64(k, __shfl_down_sync(0xFFFFFFFFu, k, o));
            if (lane == 0) {
                int i = (int)(k & 0xFFFFFFFFu);
                int j = (int)scol[i];
                out[i] = (float)j;               // FLOAT output
                sval[i] = INF;
                atomicAnd(&colfree[j >> 5], ~(1u << (j & 31)));
                pick_j = j;
                cnt = 0;
            }
        }
        __syncthreads();
        int j = pick_j;

        // ---- phase 2: collect free rows whose cached min column was taken
        #pragma unroll
        for (int q = 0; q < 4; q++) {
            int r = tid + q * 1024;
            if ((int)scol[r] == j && sval[r] < INF) {
                int p = atomicAdd(&cnt, 1);
                slist[p] = (unsigned short)r;
            }
        }
        __syncthreads();

        // ---- phase 3: rescan affected rows (whole block per row, L2 reads)
        int m = cnt;
        for (int li = 0; li < m; li++) {
            int r = slist[li];
            const float4* row = (const float4*)(g_cost + (size_t)r * NN);
            int c0 = tid * 4;
            float4 v = row[tid];
            unsigned mask = colfree[c0 >> 5];
            int sh = c0 & 31;
            unsigned long long k2 = ~0ull;
            if ((mask >> (sh + 0)) & 1)
                k2 = umin64(k2, ((unsigned long long)__float_as_uint(v.x) << 32) | (unsigned)(c0 + 0));
            if ((mask >> (sh + 1)) & 1)
                k2 = umin64(k2, ((unsigned long long)__float_as_uint(v.y) << 32) | (unsigned)(c0 + 1));
            if ((mask >> (sh + 2)) & 1)
                k2 = umin64(k2, ((unsigned long long)__float_as_uint(v.z) << 32) | (unsigned)(c0 + 2));
            if ((mask >> (sh + 3)) & 1)
                k2 = umin64(k2, ((unsigned long long)__float_as_uint(v.w) << 32) | (unsigned)(c0 + 3));
            #pragma unroll
            for (int o = 16; o; o >>= 1)
                k2 = umin64(k2, __shfl_down_sync(0xFFFFFFFFu, k2, o));
            if (lane == 0) wbest[w] = k2;
            __syncthreads();
            if (w == 0) {
                unsigned long long k = wbest[lane];
                #pragma unroll
                for (int o = 16; o; o >>= 1)
                    k = umin64(k, __shfl_down_sync(0xFFFFFFFFu, k, o));
                if (lane == 0) {
                    sval[r] = __uint_as_float((unsigned)(k >> 32));
                    scol[r] = (unsigned short)(k & 0xFFFFu);
                }
            }
            __syncthreads();
        }
    }
}

extern "C" void kernel_launch(void* const* d_in, const int* in_sizes, int n_in,
                              void* d_out, int out_size) {
    const float* x = (const float*)d_in[0];
    const float* y = (const float*)d_in[1];
    float* out = (float*)d_out;

    // norms: one warp per row -> 4096 warps = 131072 threads
    norms_kernel<<<512, 256>>>(x, y, out);
    cost_kernel<<<NN / 16, 256>>>(x, y);
    greedy_kernel<<<1, 1024>>>(out);
}

// round 6
// speedup vs baseline: 1.6167x; 1.6167x over previous
#include <cuda_runtime.h>
#include <cuda_bf16.h>
#include <cstdint>

#define NN 4096
#define DD 64

// Scratch (device globals — no allocation allowed)
__device__ float g_cost[(size_t)NN * NN];            // 64 MB
__device__ float g_costT[(size_t)NN * NN];           // 64 MB (transpose)
__device__ float g_x2[NN];
__device__ float g_y2[NN];
__device__ unsigned long long g_rowmin[NN];          // key = (cost_bits<<32) | col
__device__ unsigned long long g_colmin[NN];          // key = (cost_bits<<32) | row

__device__ __forceinline__ unsigned long long umin64(unsigned long long a, unsigned long long b) {
    return a < b ? a : b;
}
__device__ __forceinline__ unsigned long long mkkey(float v, int idx) {
    return ((unsigned long long)__float_as_uint(v) << 32) | (unsigned)idx;
}

// -------------------------------------------------------------------------
// Kernel 1: squared norms (order-insensitive per rounds 3-5 evidence) +
// init g_colmin to ~0 (graph-replay determinism) + identity prefill of out.
// -------------------------------------------------------------------------
__global__ void norms_kernel(const float* __restrict__ x, const float* __restrict__ y,
                             float* __restrict__ out) {
    int gt = blockIdx.x * blockDim.x + threadIdx.x;
    if (gt < NN) {
        out[gt] = (float)gt;
        g_colmin[gt] = ~0ull;
    }

    int w = gt >> 5;
    int lane = gt & 31;
    if (w >= NN) return;

    float2 xv = ((const float2*)(x + w * DD))[lane];
    float p = __fadd_rn(__fmul_rn(xv.x, xv.x), __fmul_rn(xv.y, xv.y));
    #pragma unroll
    for (int o = 16; o; o >>= 1)
        p = __fadd_rn(p, __shfl_down_sync(0xFFFFFFFFu, p, o));
    if (lane == 0) g_x2[w] = p;

    float2 yv = ((const float2*)(y + w * DD))[lane];
    p = __fadd_rn(__fmul_rn(yv.x, yv.x), __fmul_rn(yv.y, yv.y));
    #pragma unroll
    for (int o = 16; o; o >>= 1)
        p = __fadd_rn(p, __shfl_down_sync(0xFFFFFFFFu, p, o));
    if (lane == 0) g_y2[w] = p;
}

// -------------------------------------------------------------------------
// Kernel 2: cost matrix + per-row argmin (tie: smallest col) + per-column
// argmin contribution via global atomicMin (tie: smallest row).
// Exact fp32: sequential ascending-k FFMA chain (validated in round 5).
// -------------------------------------------------------------------------
__global__ void cost_kernel(const float* __restrict__ x, const float* __restrict__ y) {
    __shared__ float xs[16 * DD];
    __shared__ float x2s[16];
    __shared__ unsigned long long minkey[16];

    int i0 = blockIdx.x * 16;
    int tid = threadIdx.x;

    for (int k = tid; k < 16 * DD; k += 256)
        xs[k] = x[(size_t)i0 * DD + k];
    if (tid < 16) {
        x2s[tid] = g_x2[i0 + tid];
        minkey[tid] = ~0ull;
    }
    __syncthreads();

    unsigned long long lk[16];
    #pragma unroll
    for (int r = 0; r < 16; r++) lk[r] = ~0ull;

    for (int jt = 0; jt < 16; jt++) {
        int j = jt * 256 + tid;
        const float4* yr = (const float4*)(y + (size_t)j * DD);
        float4 yv[16];
        #pragma unroll
        for (int q = 0; q < 16; q++) yv[q] = yr[q];
        float y2 = g_y2[j];

        unsigned long long ck = ~0ull;   // column-j min over this block's 16 rows
        #pragma unroll
        for (int r = 0; r < 16; r++) {
            float acc = 0.0f;
            #pragma unroll
            for (int q = 0; q < 16; q++) {
                acc = __fmaf_rn(xs[r * DD + q * 4 + 0], yv[q].x, acc);
                acc = __fmaf_rn(xs[r * DD + q * 4 + 1], yv[q].y, acc);
                acc = __fmaf_rn(xs[r * DD + q * 4 + 2], yv[q].z, acc);
                acc = __fmaf_rn(xs[r * DD + q * 4 + 3], yv[q].w, acc);
            }
            float ssum = __fadd_rn(x2s[r], y2);
            float u    = __fsub_rn(ssum, __fmul_rn(2.0f, acc));
            float sq   = fmaxf(u, 0.0f);
            float c    = __fsqrt_rn(sq);
            g_cost[(size_t)(i0 + r) * NN + j] = c;
            lk[r] = umin64(lk[r], mkkey(c, j));
            ck    = umin64(ck,    mkkey(c, i0 + r));
        }
        atomicMin(&g_colmin[j], ck);
    }
    #pragma unroll
    for (int r = 0; r < 16; r++) atomicMin(&minkey[r], lk[r]);
    __syncthreads();
    if (tid < 16) g_rowmin[i0 + tid] = minkey[tid];
}

// -------------------------------------------------------------------------
// Kernel 3: 32x32 tiled transpose cost -> costT (coalesced both ways).
// -------------------------------------------------------------------------
__global__ void transpose_kernel() {
    __shared__ float t[32][33];
    int bx = blockIdx.x & 127;
    int by = blockIdx.x >> 7;
    int tx = threadIdx.x;
    int ty = threadIdx.y;        // blockDim (32, 8)

    int xc = bx * 32 + tx;
    #pragma unroll
    for (int k = 0; k < 4; k++) {
        int yr = by * 32 + ty + k * 8;
        t[ty + k * 8][tx] = g_cost[(size_t)yr * NN + xc];
    }
    __syncthreads();
    int x2 = by * 32 + tx;
    #pragma unroll
    for (int k = 0; k < 4; k++) {
        int yr = bx * 32 + ty + k * 8;
        g_costT[(size_t)yr * NN + x2] = t[tx][ty + k * 8];
    }
}

// -------------------------------------------------------------------------
// Kernel 4: parallel greedy via locally-dominant edges. Exactly equivalent
// to sorted-stable greedy. Single block, 1024 threads, while-loop rounds:
//   A) commit all mutual-pointer edges (scol[i]==j && crow[j]==i)
//   B) list free rows/cols whose cached target died this round
//   C) rescan those (warp per row/col) over free sets (bitmap-skip loads)
// Cached argmin over a shrinking set stays valid until its target dies.
// -------------------------------------------------------------------------
__global__ __launch_bounds__(1024, 1)
void match_kernel(float* __restrict__ out) {
    __shared__ unsigned short scol[NN];          // 8 KB  row -> argmin col
    __shared__ unsigned short crow[NN];          // 8 KB  col -> argmin row
    __shared__ unsigned short rlist[NN];         // 8 KB
    __shared__ unsigned short clist[NN];         // 8 KB
    __shared__ unsigned int   rowfree[NN / 32];  // 512 B
    __shared__ unsigned int   colfree[NN / 32];  // 512 B
    __shared__ int matched, cntR, cntC;

    int tid = threadIdx.x, lane = tid & 31, w = tid >> 5;

    for (int r = tid; r < NN; r += 1024) {
        scol[r] = (unsigned short)(g_rowmin[r] & 0xFFFFu);
        crow[r] = (unsigned short)(g_colmin[r] & 0xFFFFu);
    }
    for (int c = tid; c < NN / 32; c += 1024) {
        rowfree[c] = 0xFFFFFFFFu;
        colfree[c] = 0xFFFFFFFFu;
    }
    if (tid == 0) matched = 0;
    __syncthreads();

    while (true) {
        if (tid == 0) { cntR = 0; cntC = 0; }
        // ---- phase A: commit mutual edges
        #pragma unroll
        for (int q = 0; q < 4; q++) {
            int i = tid + q * 1024;
            if ((rowfree[i >> 5] >> (i & 31)) & 1) {
                int j = scol[i];
                if ((int)crow[j] == i) {
                    out[i] = (float)j;
                    atomicAnd(&rowfree[i >> 5], ~(1u << (i & 31)));
                    atomicAnd(&colfree[j >> 5], ~(1u << (j & 31)));
                    atomicAdd(&matched, 1);
                }
            }
        }
        __syncthreads();
        if (matched == NN) break;

        // ---- phase B: who needs a rescan
        #pragma unroll
        for (int q = 0; q < 4; q++) {
            int i = tid + q * 1024;
            if ((rowfree[i >> 5] >> (i & 31)) & 1) {
                int j = scol[i];
                if (!((colfree[j >> 5] >> (j & 31)) & 1)) {
                    int p = atomicAdd(&cntR, 1);
                    rlist[p] = (unsigned short)i;
                }
            }
            int j = i;
            if ((colfree[j >> 5] >> (j & 31)) & 1) {
                int i2 = crow[j];
                if (!((rowfree[i2 >> 5] >> (i2 & 31)) & 1)) {
                    int p = atomicAdd(&cntC, 1);
                    clist[p] = (unsigned short)j;
                }
            }
        }
        __syncthreads();
        int nR = cntR, nC = cntC;

        // ---- phase C: rescans, one warp per row/col
        for (int e = w; e < nR + nC; e += 32) {
            bool isRow = e < nR;
            int idx = isRow ? (int)rlist[e] : (int)clist[e - nR];
            const float4* base =
                (const float4*)((isRow ? g_cost : g_costT) + (size_t)idx * NN);
            const unsigned int* fb = isRow ? colfree : rowfree;
            unsigned long long best = ~0ull;
            for (int b = lane; b < NN / 4; b += 32) {
                int c0 = b * 4;
                unsigned m = (fb[c0 >> 5] >> (c0 & 31)) & 0xFu;
                if (m) {
                    float4 v = base[b];
                    if (m & 1) best = umin64(best, mkkey(v.x, c0 + 0));
                    if (m & 2) best = umin64(best, mkkey(v.y, c0 + 1));
                    if (m & 4) best = umin64(best, mkkey(v.z, c0 + 2));
                    if (m & 8) best = umin64(best, mkkey(v.w, c0 + 3));
                }
            }
            #pragma unroll
            for (int o = 16; o; o >>= 1)
                best = umin64(best, __shfl_down_sync(0xFFFFFFFFu, best, o));
            if (lane == 0) {
                if (isRow) scol[idx] = (unsigned short)(best & 0xFFFFu);
                else       crow[idx] = (unsigned short)(best & 0xFFFFu);
            }
        }
        __syncthreads();
    }
}

extern "C" void kernel_launch(void* const* d_in, const int* in_sizes, int n_in,
                              void* d_out, int out_size) {
    const float* x = (const float*)d_in[0];
    const float* y = (const float*)d_in[1];
    float* out = (float*)d_out;

    norms_kernel<<<512, 256>>>(x, y, out);
    cost_kernel<<<NN / 16, 256>>>(x, y);
    transpose_kernel<<<128 * 128, dim3(32, 8)>>>();
    match_kernel<<<1, 1024>>>(out);
}

// round 8
// speedup vs baseline: 1.8691x; 1.1561x over previous
#include <cuda_runtime.h>
#include <cuda_bf16.h>
#include <cstdint>

#define NN 4096
#define DD 64

// Scratch (device globals — no allocation allowed)
__device__ float g_cost[(size_t)NN * NN];            // 64 MB
__device__ float g_costT[(size_t)NN * NN];           // 64 MB (transpose)
__device__ float g_x2[NN];
__device__ float g_y2[NN];
__device__ unsigned long long g_rowmin[NN];          // key = (cost_bits<<32) | col
__device__ unsigned long long g_colmin[NN];          // key = (cost_bits<<32) | row

__device__ __forceinline__ unsigned long long umin64(unsigned long long a, unsigned long long b) {
    return a < b ? a : b;
}
__device__ __forceinline__ unsigned long long mkkey(float v, int idx) {
    return ((unsigned long long)__float_as_uint(v) << 32) | (unsigned)idx;
}

// -------------------------------------------------------------------------
// Kernel 1: squared norms (order-insensitive per rounds 3-5 evidence) +
// re-init g_rowmin/g_colmin every replay (both are atomicMin-accumulated) +
// identity prefill of out.
// -------------------------------------------------------------------------
__global__ void norms_kernel(const float* __restrict__ x, const float* __restrict__ y,
                             float* __restrict__ out) {
    int gt = blockIdx.x * blockDim.x + threadIdx.x;
    if (gt < NN) {
        out[gt] = (float)gt;
        g_rowmin[gt] = ~0ull;
        g_colmin[gt] = ~0ull;
    }

    int w = gt >> 5;
    int lane = gt & 31;
    if (w >= NN) return;

    float2 xv = ((const float2*)(x + w * DD))[lane];
    float p = __fadd_rn(__fmul_rn(xv.x, xv.x), __fmul_rn(xv.y, xv.y));
    #pragma unroll
    for (int o = 16; o; o >>= 1)
        p = __fadd_rn(p, __shfl_down_sync(0xFFFFFFFFu, p, o));
    if (lane == 0) g_x2[w] = p;

    float2 yv = ((const float2*)(y + w * DD))[lane];
    p = __fadd_rn(__fmul_rn(yv.x, yv.x), __fmul_rn(yv.y, yv.y));
    #pragma unroll
    for (int o = 16; o; o >>= 1)
        p = __fadd_rn(p, __shfl_down_sync(0xFFFFFFFFu, p, o));
    if (lane == 0) g_y2[w] = p;
}

// -------------------------------------------------------------------------
// Kernel 2: SGEMM-tiled cost build, 64x64 tile per 256-thread block,
// 4x4 microtile per thread (16 accs, no spills). Fuses:
//   - g_cost write (row-major, direct from regs, coalesced)
//   - g_costT write (via shared re-staging, coalesced)
//   - per-row / per-col argmin (thread reduce -> shared atomicMin -> global)
// Numerics: per output a single ascending-k __fmaf_rn chain + the exact
// validated epilogue -> bit-identical costs to the round-5/6 kernel.
// -------------------------------------------------------------------------
#define TSTR 68   // shared stride in floats (68*4 = 272 B, 16B-aligned)

__global__ __launch_bounds__(256)
void cost_kernel(const float* __restrict__ x, const float* __restrict__ y) {
    __shared__ __align__(16) float xsh[DD * TSTR];   // [k][i]
    __shared__ __align__(16) float ysh[DD * TSTR];   // [k][j]
    __shared__ unsigned long long srmin[64], scmin[64];

    int i0 = blockIdx.y * 64, j0 = blockIdx.x * 64;
    int tid = threadIdx.x;
    int tx = tid & 15, ty = tid >> 4;

    if (tid < 64) srmin[tid] = ~0ull;
    else if (tid < 128) scmin[tid - 64] = ~0ull;

    // Load tiles transposed into shared: row r = tid>>2, k-chunk = (tid&3)*16
    {
        int r = tid >> 2, k0 = (tid & 3) * 16;
        const float4* px = (const float4*)(x + (size_t)(i0 + r) * DD + k0);
        const float4* py = (const float4*)(y + (size_t)(j0 + r) * DD + k0);
        #pragma unroll
        for (int q = 0; q < 4; q++) {
            float4 v = px[q];
            xsh[(k0 + q * 4 + 0) * TSTR + r] = v.x;
            xsh[(k0 + q * 4 + 1) * TSTR + r] = v.y;
            xsh[(k0 + q * 4 + 2) * TSTR + r] = v.z;
            xsh[(k0 + q * 4 + 3) * TSTR + r] = v.w;
            float4 u = py[q];
            ysh[(k0 + q * 4 + 0) * TSTR + r] = u.x;
            ysh[(k0 + q * 4 + 1) * TSTR + r] = u.y;
            ysh[(k0 + q * 4 + 2) * TSTR + r] = u.z;
            ysh[(k0 + q * 4 + 3) * TSTR + r] = u.w;
        }
    }
    __syncthreads();

    float acc[4][4];
    #pragma unroll
    for (int a = 0; a < 4; a++)
        #pragma unroll
        for (int b = 0; b < 4; b++) acc[a][b] = 0.0f;

    #pragma unroll
    for (int k = 0; k < DD; k++) {
        float4 xv = *(const float4*)&xsh[k * TSTR + ty * 4];
        float4 yv = *(const float4*)&ysh[k * TSTR + tx * 4];
        float xa[4] = {xv.x, xv.y, xv.z, xv.w};
        float ya[4] = {yv.x, yv.y, yv.z, yv.w};
        #pragma unroll
        for (int a = 0; a < 4; a++)
            #pragma unroll
            for (int b = 0; b < 4; b++)
                acc[a][b] = __fmaf_rn(xa[a], ya[b], acc[a][b]);
    }

    // Epilogue: exact validated sequence per element
    float x2v[4], y2v[4];
    #pragma unroll
    for (int a = 0; a < 4; a++) {
        x2v[a] = g_x2[i0 + ty * 4 + a];
        y2v[a] = g_y2[j0 + tx * 4 + a];
    }
    #pragma unroll
    for (int a = 0; a < 4; a++)
        #pragma unroll
        for (int b = 0; b < 4; b++) {
            float ssum = __fadd_rn(x2v[a], y2v[b]);
            float u    = __fsub_rn(ssum, __fmul_rn(2.0f, acc[a][b]));
            float sq   = fmaxf(u, 0.0f);
            acc[a][b]  = __fsqrt_rn(sq);
        }

    // Per-thread minima -> shared atomicMin
    #pragma unroll
    for (int a = 0; a < 4; a++) {
        unsigned long long rk = ~0ull;
        #pragma unroll
        for (int b = 0; b < 4; b++)
            rk = umin64(rk, mkkey(acc[a][b], j0 + tx * 4 + b));
        atomicMin(&srmin[ty * 4 + a], rk);
    }
    #pragma unroll
    for (int b = 0; b < 4; b++) {
        unsigned long long ck = ~0ull;
        #pragma unroll
        for (int a = 0; a < 4; a++)
            ck = umin64(ck, mkkey(acc[a][b], i0 + ty * 4 + a));
        atomicMin(&scmin[tx * 4 + b], ck);
    }

    // Direct row-major write of g_cost (coalesced float4 per microrow)
    #pragma unroll
    for (int a = 0; a < 4; a++) {
        float4 o = make_float4(acc[a][0], acc[a][1], acc[a][2], acc[a][3]);
        *(float4*)&g_cost[(size_t)(i0 + ty * 4 + a) * NN + j0 + tx * 4] = o;
    }

    __syncthreads();                  // all xsh/ysh reads done; atomics visible
    // Stage transposed tile into xsh: [c][r]
    #pragma unroll
    for (int a = 0; a < 4; a++)
        #pragma unroll
        for (int b = 0; b < 4; b++)
            xsh[(tx * 4 + b) * TSTR + ty * 4 + a] = acc[a][b];
    __syncthreads();

    // Coalesced write of g_costT
    {
        int c = tid >> 2, k0 = (tid & 3) * 16;
        #pragma unroll
        for (int q = 0; q < 4; q++) {
            float4 v = *(const float4*)&xsh[c * TSTR + k0 + q * 4];
            *(float4*)&g_costT[(size_t)(j0 + c) * NN + i0 + k0 + q * 4] = v;
        }
    }

    // Global minima
    if (tid < 64) atomicMin(&g_rowmin[i0 + tid], srmin[tid]);
    else if (tid < 128) atomicMin(&g_colmin[j0 + tid - 64], scmin[tid - 64]);
}

// -------------------------------------------------------------------------
// Kernel 3: parallel greedy via locally-dominant edges (exact sorted-greedy
// equivalence, validated round 6). Single block, 1024 threads.
// -------------------------------------------------------------------------
__global__ __launch_bounds__(1024, 1)
void match_kernel(float* __restrict__ out) {
    __shared__ unsigned short scol[NN];          // 8 KB  row -> argmin col
    __shared__ unsigned short crow[NN];          // 8 KB  col -> argmin row
    __shared__ unsigned short rlist[NN];         // 8 KB
    __shared__ unsigned short clist[NN];         // 8 KB
    __shared__ unsigned int   rowfree[NN / 32];  // 512 B
    __shared__ unsigned int   colfree[NN / 32];  // 512 B
    __shared__ int matched, cntR, cntC;

    int tid = threadIdx.x, lane = tid & 31, w = tid >> 5;

    for (int r = tid; r < NN; r += 1024) {
        scol[r] = (unsigned short)(g_rowmin[r] & 0xFFFFu);
        crow[r] = (unsigned short)(g_colmin[r] & 0xFFFFu);
    }
    for (int c = tid; c < NN / 32; c += 1024) {
        rowfree[c] = 0xFFFFFFFFu;
        colfree[c] = 0xFFFFFFFFu;
    }
    if (tid == 0) matched = 0;
    __syncthreads();

    while (true) {
        if (tid == 0) { cntR = 0; cntC = 0; }
        // ---- phase A: commit mutual edges
        #pragma unroll
        for (int q = 0; q < 4; q++) {
            int i = tid + q * 1024;
            if ((rowfree[i >> 5] >> (i & 31)) & 1) {
                int j = scol[i];
                if ((int)crow[j] == i) {
                    out[i] = (float)j;
                    atomicAnd(&rowfree[i >> 5], ~(1u << (i & 31)));
                    atomicAnd(&colfree[j >> 5], ~(1u << (j & 31)));
                    atomicAdd(&matched, 1);
                }
            }
        }
        __syncthreads();
        if (matched == NN) break;

        // ---- phase B: who needs a rescan
        #pragma unroll
        for (int q = 0; q < 4; q++) {
            int i = tid + q * 1024;
            if ((rowfree[i >> 5] >> (i & 31)) & 1) {
                int j = scol[i];
                if (!((colfree[j >> 5] >> (j & 31)) & 1)) {
                    int p = atomicAdd(&cntR, 1);
                    rlist[p] = (unsigned short)i;
                }
            }
            int j = i;
            if ((colfree[j >> 5] >> (j & 31)) & 1) {
                int i2 = crow[j];
                if (!((rowfree[i2 >> 5] >> (i2 & 31)) & 1)) {
                    int p = atomicAdd(&cntC, 1);
                    clist[p] = (unsigned short)j;
                }
            }
        }
        __syncthreads();
        int nR = cntR, nC = cntC;

        // ---- phase C: rescans, one warp per row/col
        for (int e = w; e < nR + nC; e += 32) {
            bool isRow = e < nR;
            int idx = isRow ? (int)rlist[e] : (int)clist[e - nR];
            const float4* base =
                (const float4*)((isRow ? g_cost : g_costT) + (size_t)idx * NN);
            const unsigned int* fb = isRow ? colfree : rowfree;
            unsigned long long best = ~0ull;
            for (int b = lane; b < NN / 4; b += 32) {
                int c0 = b * 4;
                unsigned m = (fb[c0 >> 5] >> (c0 & 31)) & 0xFu;
                if (m) {
                    float4 v = base[b];
                    if (m & 1) best = umin64(best, mkkey(v.x, c0 + 0));
                    if (m & 2) best = umin64(best, mkkey(v.y, c0 + 1));
                    if (m & 4) best = umin64(best, mkkey(v.z, c0 + 2));
                    if (m & 8) best = umin64(best, mkkey(v.w, c0 + 3));
                }
            }
            #pragma unroll
            for (int o = 16; o; o >>= 1)
                best = umin64(best, __shfl_down_sync(0xFFFFFFFFu, best, o));
            if (lane == 0) {
                if (isRow) scol[idx] = (unsigned short)(best & 0xFFFFu);
                else       crow[idx] = (unsigned short)(best & 0xFFFFu);
            }
        }
        __syncthreads();
    }
}

extern "C" void kernel_launch(void* const* d_in, const int* in_sizes, int n_in,
                              void* d_out, int out_size) {
    const float* x = (const float*)d_in[0];
    const float* y = (const float*)d_in[1];
    float* out = (float*)d_out;

    norms_kernel<<<512, 256>>>(x, y, out);
    cost_kernel<<<dim3(64, 64), 256>>>(x, y);
    match_kernel<<<1, 1024>>>(out);
}

// round 9
// speedup vs baseline: 11.2691x; 6.0292x over previous
#include <cuda_runtime.h>
#include <cuda_bf16.h>
#include <cstdint>

#define NN 4096
#define DD 64

// Scratch (device globals — no allocation allowed)
__device__ float g_cost[(size_t)NN * NN];            // 64 MB
__device__ float g_costT[(size_t)NN * NN];           // 64 MB (transpose)
__device__ float g_x2[NN];
__device__ float g_y2[NN];
__device__ unsigned long long g_rowmin[NN];          // key = (cost_bits<<32) | col
__device__ unsigned long long g_colmin[NN];          // key = (cost_bits<<32) | row
__device__ unsigned long long g_rowseg[(size_t)NN * 64];  // per-row per-64col segment min
__device__ unsigned long long g_colseg[(size_t)NN * 64];  // per-col per-64row segment min
__device__ unsigned short g_scol[NN];                // row -> cached argmin col
__device__ unsigned short g_crow[NN];                // col -> cached argmin row
__device__ unsigned int g_rowfreeG[NN / 32];
__device__ unsigned int g_colfreeG[NN / 32];
__device__ int g_matched;

__device__ __forceinline__ unsigned long long umin64(unsigned long long a, unsigned long long b) {
    return a < b ? a : b;
}
__device__ __forceinline__ unsigned long long mkkey(float v, int idx) {
    return ((unsigned long long)__float_as_uint(v) << 32) | (unsigned)idx;
}

// -------------------------------------------------------------------------
// Kernel 1: squared norms + re-init of atomicMin accumulators + out prefill.
// -------------------------------------------------------------------------
__global__ void norms_kernel(const float* __restrict__ x, const float* __restrict__ y,
                             float* __restrict__ out) {
    int gt = blockIdx.x * blockDim.x + threadIdx.x;
    if (gt < NN) {
        out[gt] = (float)gt;
        g_rowmin[gt] = ~0ull;
        g_colmin[gt] = ~0ull;
    }

    int w = gt >> 5;
    int lane = gt & 31;
    if (w >= NN) return;

    float2 xv = ((const float2*)(x + w * DD))[lane];
    float p = __fadd_rn(__fmul_rn(xv.x, xv.x), __fmul_rn(xv.y, xv.y));
    #pragma unroll
    for (int o = 16; o; o >>= 1)
        p = __fadd_rn(p, __shfl_down_sync(0xFFFFFFFFu, p, o));
    if (lane == 0) g_x2[w] = p;

    float2 yv = ((const float2*)(y + w * DD))[lane];
    p = __fadd_rn(__fmul_rn(yv.x, yv.x), __fmul_rn(yv.y, yv.y));
    #pragma unroll
    for (int o = 16; o; o >>= 1)
        p = __fadd_rn(p, __shfl_down_sync(0xFFFFFFFFu, p, o));
    if (lane == 0) g_y2[w] = p;
}

// -------------------------------------------------------------------------
// Kernel 2: SGEMM-tiled cost build (validated bit-exact). Additionally
// stores the per-tile row/col minima as SEGMENT minima (the tile IS a
// 64-wide segment) for the hierarchical rescan.
// -------------------------------------------------------------------------
#define TSTR 68   // shared stride in floats (16B-aligned)

__global__ __launch_bounds__(256)
void cost_kernel(const float* __restrict__ x, const float* __restrict__ y) {
    __shared__ __align__(16) float xsh[DD * TSTR];   // [k][i]
    __shared__ __align__(16) float ysh[DD * TSTR];   // [k][j]
    __shared__ unsigned long long srmin[64], scmin[64];

    int i0 = blockIdx.y * 64, j0 = blockIdx.x * 64;
    int tid = threadIdx.x;
    int tx = tid & 15, ty = tid >> 4;

    if (tid < 64) srmin[tid] = ~0ull;
    else if (tid < 128) scmin[tid - 64] = ~0ull;

    {
        int r = tid >> 2, k0 = (tid & 3) * 16;
        const float4* px = (const float4*)(x + (size_t)(i0 + r) * DD + k0);
        const float4* py = (const float4*)(y + (size_t)(j0 + r) * DD + k0);
        #pragma unroll
        for (int q = 0; q < 4; q++) {
            float4 v = px[q];
            xsh[(k0 + q * 4 + 0) * TSTR + r] = v.x;
            xsh[(k0 + q * 4 + 1) * TSTR + r] = v.y;
            xsh[(k0 + q * 4 + 2) * TSTR + r] = v.z;
            xsh[(k0 + q * 4 + 3) * TSTR + r] = v.w;
            float4 u = py[q];
            ysh[(k0 + q * 4 + 0) * TSTR + r] = u.x;
            ysh[(k0 + q * 4 + 1) * TSTR + r] = u.y;
            ysh[(k0 + q * 4 + 2) * TSTR + r] = u.z;
            ysh[(k0 + q * 4 + 3) * TSTR + r] = u.w;
        }
    }
    __syncthreads();

    float acc[4][4];
    #pragma unroll
    for (int a = 0; a < 4; a++)
        #pragma unroll
        for (int b = 0; b < 4; b++) acc[a][b] = 0.0f;

    #pragma unroll
    for (int k = 0; k < DD; k++) {
        float4 xv = *(const float4*)&xsh[k * TSTR + ty * 4];
        float4 yv = *(const float4*)&ysh[k * TSTR + tx * 4];
        float xa[4] = {xv.x, xv.y, xv.z, xv.w};
        float ya[4] = {yv.x, yv.y, yv.z, yv.w};
        #pragma unroll
        for (int a = 0; a < 4; a++)
            #pragma unroll
            for (int b = 0; b < 4; b++)
                acc[a][b] = __fmaf_rn(xa[a], ya[b], acc[a][b]);
    }

    float x2v[4], y2v[4];
    #pragma unroll
    for (int a = 0; a < 4; a++) {
        x2v[a] = g_x2[i0 + ty * 4 + a];
        y2v[a] = g_y2[j0 + tx * 4 + a];
    }
    #pragma unroll
    for (int a = 0; a < 4; a++)
        #pragma unroll
        for (int b = 0; b < 4; b++) {
            float ssum = __fadd_rn(x2v[a], y2v[b]);
            float u    = __fsub_rn(ssum, __fmul_rn(2.0f, acc[a][b]));
            float sq   = fmaxf(u, 0.0f);
            acc[a][b]  = __fsqrt_rn(sq);
        }

    #pragma unroll
    for (int a = 0; a < 4; a++) {
        unsigned long long rk = ~0ull;
        #pragma unroll
        for (int b = 0; b < 4; b++)
            rk = umin64(rk, mkkey(acc[a][b], j0 + tx * 4 + b));
        atomicMin(&srmin[ty * 4 + a], rk);
    }
    #pragma unroll
    for (int b = 0; b < 4; b++) {
        unsigned long long ck = ~0ull;
        #pragma unroll
        for (int a = 0; a < 4; a++)
            ck = umin64(ck, mkkey(acc[a][b], i0 + ty * 4 + a));
        atomicMin(&scmin[tx * 4 + b], ck);
    }

    #pragma unroll
    for (int a = 0; a < 4; a++) {
        float4 o = make_float4(acc[a][0], acc[a][1], acc[a][2], acc[a][3]);
        *(float4*)&g_cost[(size_t)(i0 + ty * 4 + a) * NN + j0 + tx * 4] = o;
    }

    __syncthreads();
    #pragma unroll
    for (int a = 0; a < 4; a++)
        #pragma unroll
        for (int b = 0; b < 4; b++)
            xsh[(tx * 4 + b) * TSTR + ty * 4 + a] = acc[a][b];
    __syncthreads();

    {
        int c = tid >> 2, k0 = (tid & 3) * 16;
        #pragma unroll
        for (int q = 0; q < 4; q++) {
            float4 v = *(const float4*)&xsh[c * TSTR + k0 + q * 4];
            *(float4*)&g_costT[(size_t)(j0 + c) * NN + i0 + k0 + q * 4] = v;
        }
    }

    if (tid < 64) {
        g_rowseg[(size_t)(i0 + tid) * 64 + blockIdx.x] = srmin[tid];
        atomicMin(&g_rowmin[i0 + tid], srmin[tid]);
    } else if (tid < 128) {
        int c = tid - 64;
        g_colseg[(size_t)(j0 + c) * 64 + blockIdx.y] = scmin[c];
        atomicMin(&g_colmin[j0 + c], scmin[c]);
    }
}

// -------------------------------------------------------------------------
// Kernel 3: init match state from the global minima.
// -------------------------------------------------------------------------
__global__ void init_kernel() {
    int i = blockIdx.x * blockDim.x + threadIdx.x;
    if (i < NN) {
        g_scol[i] = (unsigned short)(g_rowmin[i] & 0xFFFFu);
        g_crow[i] = (unsigned short)(g_colmin[i] & 0xFFFFu);
    }
    if (i < NN / 32) { g_rowfreeG[i] = ~0u; g_colfreeG[i] = ~0u; }
    if (i == 0) g_matched = 0;
}

// -------------------------------------------------------------------------
// Kernel 4: commit all mutual-pointer edges (locally dominant; exact greedy
// equivalence — invariant: at commit time every free row/col pointer
// targets a live opposite, restored by the preceding rescan).
// -------------------------------------------------------------------------
__global__ void commit_kernel(float* __restrict__ out) {
    int i = blockIdx.x * blockDim.x + threadIdx.x;
    if (!((g_rowfreeG[i >> 5] >> (i & 31)) & 1)) return;
    int j = g_scol[i];
    if ((int)g_crow[j] == i) {
        out[i] = (float)j;
        atomicAnd(&g_rowfreeG[i >> 5], ~(1u << (i & 31)));
        atomicAnd(&g_colfreeG[j >> 5], ~(1u << (j & 31)));
        atomicAdd(&g_matched, 1);
    }
}

// -------------------------------------------------------------------------
// Kernel 5: warp-per-row/col rescan using segment minima. Only rows/cols
// whose cached target died do work; a cached segment min stays valid while
// its column lives (free sets only shrink), dead segments recomputed from
// g_cost/g_costT masked by the free bitmap.
// -------------------------------------------------------------------------
__global__ void rescan_kernel() {
    int gt = blockIdx.x * blockDim.x + threadIdx.x;
    int gw = gt >> 5, lane = gt & 31;
    bool isRow = gw < NN;
    int idx = isRow ? gw : gw - NN;
    const unsigned int* ofb = isRow ? g_colfreeG : g_rowfreeG;
    const unsigned int* sfb = isRow ? g_rowfreeG : g_colfreeG;
    if (!((sfb[idx >> 5] >> (idx & 31)) & 1)) return;
    int tgt = isRow ? (int)g_scol[idx] : (int)g_crow[idx];
    if ((ofb[tgt >> 5] >> (tgt & 31)) & 1) return;      // cached argmin still valid

    unsigned long long* seg = (isRow ? g_rowseg : g_colseg) + (size_t)idx * 64;
    const float* base = (isRow ? g_cost : g_costT) + (size_t)idx * NN;
    unsigned long long best = ~0ull;
    #pragma unroll
    for (int s0 = 0; s0 < 64; s0 += 32) {
        int s = s0 + lane;
        unsigned long long k = seg[s];
        if (k != ~0ull) {
            int c = (int)(k & 0xFFFFu);
            if (!((ofb[c >> 5] >> (c & 31)) & 1)) {
                unsigned long long nk = ~0ull;
                unsigned w0 = ofb[s * 2], w1 = ofb[s * 2 + 1];
                int c0 = s * 64;
                if (w0 | w1) {
                    const float4* p = (const float4*)(base + c0);
                    #pragma unroll
                    for (int q = 0; q < 16; q++) {
                        unsigned mm = ((q < 8 ? w0 : w1) >> ((q & 7) * 4)) & 0xFu;
                        if (mm) {
                            float4 v = p[q];
                            if (mm & 1) nk = umin64(nk, mkkey(v.x, c0 + q * 4 + 0));
                            if (mm & 2) nk = umin64(nk, mkkey(v.y, c0 + q * 4 + 1));
                            if (mm & 4) nk = umin64(nk, mkkey(v.z, c0 + q * 4 + 2));
                            if (mm & 8) nk = umin64(nk, mkkey(v.w, c0 + q * 4 + 3));
                        }
                    }
                }
                seg[s] = nk;
                k = nk;
            }
        }
        best = umin64(best, k);
    }
    #pragma unroll
    for (int o = 16; o; o >>= 1)
        best = umin64(best, __shfl_down_sync(0xFFFFFFFFu, best, o));
    if (lane == 0) {
        if (isRow) g_scol[idx] = (unsigned short)(best & 0xFFFFu);
        else       g_crow[idx] = (unsigned short)(best & 0xFFFFu);
    }
}

// -------------------------------------------------------------------------
// Kernel 6: single-block finisher — loops commit/rescan (seg-based) on the
// tail until complete. Usually near-no-op after the multi-SM rounds, but
// guarantees termination regardless.
// -------------------------------------------------------------------------
__global__ __launch_bounds__(1024, 1)
void finish_kernel(float* __restrict__ out) {
    __shared__ unsigned short scol[NN], crow[NN], rlist[NN], clist[NN];
    __shared__ unsigned int rowfree[NN / 32], colfree[NN / 32];
    __shared__ int matched, cntR, cntC;

    int tid = threadIdx.x, lane = tid & 31, w = tid >> 5;

    for (int r = tid; r < NN; r += 1024) { scol[r] = g_scol[r]; crow[r] = g_crow[r]; }
    for (int c = tid; c < NN / 32; c += 1024) { rowfree[c] = g_rowfreeG[c]; colfree[c] = g_colfreeG[c]; }
    if (tid == 0) matched = g_matched;
    __syncthreads();

    while (true) {
        if (tid == 0) { cntR = 0; cntC = 0; }
        #pragma unroll
        for (int q = 0; q < 4; q++) {
            int i = tid + q * 1024;
            if ((rowfree[i >> 5] >> (i & 31)) & 1) {
                int j = scol[i];
                if ((int)crow[j] == i) {
                    out[i] = (float)j;
                    atomicAnd(&rowfree[i >> 5], ~(1u << (i & 31)));
                    atomicAnd(&colfree[j >> 5], ~(1u << (j & 31)));
                    atomicAdd(&matched, 1);
                }
            }
        }
        __syncthreads();
        if (matched == NN) break;

        #pragma unroll
        for (int q = 0; q < 4; q++) {
            int i = tid + q * 1024;
            if ((rowfree[i >> 5] >> (i & 31)) & 1) {
                int j = scol[i];
                if (!((colfree[j >> 5] >> (j & 31)) & 1)) {
                    int p = atomicAdd(&cntR, 1);
                    rlist[p] = (unsigned short)i;
                }
            }
            if ((colfree[i >> 5] >> (i & 31)) & 1) {
                int r2 = crow[i];
                if (!((rowfree[r2 >> 5] >> (r2 & 31)) & 1)) {
                    int p = atomicAdd(&cntC, 1);
                    clist[p] = (unsigned short)i;
                }
            }
        }
        __syncthreads();
        int nR = cntR, nC = cntC;

        for (int e = w; e < nR + nC; e += 32) {
            bool isRow = e < nR;
            int idx = isRow ? (int)rlist[e] : (int)clist[e - nR];
            unsigned long long* seg = (isRow ? g_rowseg : g_colseg) + (size_t)idx * 64;
            const float* base = (isRow ? g_cost : g_costT) + (size_t)idx * NN;
            const unsigned int* ofb = isRow ? colfree : rowfree;
            unsigned long long best = ~0ull;
            #pragma unroll
            for (int s0 = 0; s0 < 64; s0 += 32) {
                int s = s0 + lane;
                unsigned long long k = seg[s];
                if (k != ~0ull) {
                    int c = (int)(k & 0xFFFFu);
                    if (!((ofb[c >> 5] >> (c & 31)) & 1)) {
                        unsigned long long nk = ~0ull;
                        unsigned w0 = ofb[s * 2], w1 = ofb[s * 2 + 1];
                        int c0 = s * 64;
                        if (w0 | w1) {
                            const float4* p = (const float4*)(base + c0);
                            #pragma unroll
                            for (int q = 0; q < 16; q++) {
                                unsigned mm = ((q < 8 ? w0 : w1) >> ((q & 7) * 4)) & 0xFu;
                                if (mm) {
                                    float4 v = p[q];
                                    if (mm & 1) nk = umin64(nk, mkkey(v.x, c0 + q * 4 + 0));
                                    if (mm & 2) nk = umin64(nk, mkkey(v.y, c0 + q * 4 + 1));
                                    if (mm & 4) nk = umin64(nk, mkkey(v.z, c0 + q * 4 + 2));
                                    if (mm & 8) nk = umin64(nk, mkkey(v.w, c0 + q * 4 + 3));
                                }
                            }
                        }
                        seg[s] = nk;
                        k = nk;
                    }
                }
                best = umin64(best, k);
            }
            #pragma unroll
            for (int o = 16; o; o >>= 1)
                best = umin64(best, __shfl_down_sync(0xFFFFFFFFu, best, o));
            if (lane == 0) {
                if (isRow) scol[idx] = (unsigned short)(best & 0xFFFFu);
                else       crow[idx] = (unsigned short)(best & 0xFFFFu);
            }
        }
        __syncthreads();
    }
}

extern "C" void kernel_launch(void* const* d_in, const int* in_sizes, int n_in,
                              void* d_out, int out_size) {
    const float* x = (const float*)d_in[0];
    const float* y = (const float*)d_in[1];
    float* out = (float*)d_out;

    norms_kernel<<<512, 256>>>(x, y, out);
    cost_kernel<<<dim3(64, 64), 256>>>(x, y);
    init_kernel<<<4, 1024>>>();
    for (int r = 0; r < 8; r++) {
        commit_kernel<<<4, 1024>>>(out);
        rescan_kernel<<<256, 1024>>>();
    }
    finish_kernel<<<1, 1024>>>(out);
}

// round 11
// speedup vs baseline: 18.1026x; 1.6064x over previous
#include <cuda_runtime.h>
#include <cuda_bf16.h>
#include <cstdint>

#define NN 4096
#define DD 64
#define NBLK 128   // persistent matcher blocks (<=148 SMs -> co-resident)

// Scratch (device globals — no allocation allowed)
__device__ float g_cost[(size_t)NN * NN];            // 64 MB
__device__ float g_costT[(size_t)NN * NN];           // 64 MB (transpose)
__device__ float g_x2[NN];
__device__ float g_y2[NN];
__device__ unsigned long long g_rowmin[NN];          // key = (cost_bits<<32) | col
__device__ unsigned long long g_colmin[NN];          // key = (cost_bits<<32) | row
__device__ unsigned long long g_rowseg[(size_t)NN * 64];  // per-row per-64col segment min
__device__ unsigned long long g_colseg[(size_t)NN * 64];  // per-col per-64row segment min
__device__ unsigned short g_scol[NN];                // row -> cached argmin col
__device__ unsigned short g_crow[NN];                // col -> cached argmin row
__device__ unsigned int g_rowfreeG[NN / 32];
__device__ unsigned int g_colfreeG[NN / 32];
__device__ int g_matched;
__device__ int g_bar_cnt;
__device__ int g_bar_gen;

__device__ __forceinline__ unsigned long long umin64(unsigned long long a, unsigned long long b) {
    return a < b ? a : b;
}
__device__ __forceinline__ unsigned long long mkkey(float v, int idx) {
    return ((unsigned long long)__float_as_uint(v) << 32) | (unsigned)idx;
}

// Software grid barrier (all blocks co-resident; sense-reversing generation).
__device__ __forceinline__ void gridsync() {
    __threadfence();
    __syncthreads();
    if (threadIdx.x == 0) {
        int gen = atomicAdd(&g_bar_gen, 0);
        if (atomicAdd(&g_bar_cnt, 1) == NBLK - 1) {
            g_bar_cnt = 0;
            __threadfence();
            atomicExch(&g_bar_gen, gen + 1);
        } else {
            while (atomicAdd(&g_bar_gen, 0) == gen) __nanosleep(64);
        }
    }
    __syncthreads();
}

// -------------------------------------------------------------------------
// Kernel 1: squared norms + re-init of atomicMin accumulators + out prefill.
// -------------------------------------------------------------------------
__global__ void norms_kernel(const float* __restrict__ x, const float* __restrict__ y,
                             float* __restrict__ out) {
    int gt = blockIdx.x * blockDim.x + threadIdx.x;
    if (gt < NN) {
        out[gt] = (float)gt;
        g_rowmin[gt] = ~0ull;
        g_colmin[gt] = ~0ull;
    }

    int w = gt >> 5;
    int lane = gt & 31;
    if (w >= NN) return;

    float2 xv = ((const float2*)(x + w * DD))[lane];
    float p = __fadd_rn(__fmul_rn(xv.x, xv.x), __fmul_rn(xv.y, xv.y));
    #pragma unroll
    for (int o = 16; o; o >>= 1)
        p = __fadd_rn(p, __shfl_down_sync(0xFFFFFFFFu, p, o));
    if (lane == 0) g_x2[w] = p;

    float2 yv = ((const float2*)(y + w * DD))[lane];
    p = __fadd_rn(__fmul_rn(yv.x, yv.x), __fmul_rn(yv.y, yv.y));
    #pragma unroll
    for (int o = 16; o; o >>= 1)
        p = __fadd_rn(p, __shfl_down_sync(0xFFFFFFFFu, p, o));
    if (lane == 0) g_y2[w] = p;
}

// -------------------------------------------------------------------------
// Kernel 2: SGEMM-tiled cost build (validated bit-exact), fused cost+costT
// writes, per-row/col global argmins, and 64-wide SEGMENT minima.
// -------------------------------------------------------------------------
#define TSTR 68   // shared stride in floats (16B-aligned)

__global__ __launch_bounds__(256)
void cost_kernel(const float* __restrict__ x, const float* __restrict__ y) {
    __shared__ __align__(16) float xsh[DD * TSTR];   // [k][i]
    __shared__ __align__(16) float ysh[DD * TSTR];   // [k][j]
    __shared__ unsigned long long srmin[64], scmin[64];

    int i0 = blockIdx.y * 64, j0 = blockIdx.x * 64;
    int tid = threadIdx.x;
    int tx = tid & 15, ty = tid >> 4;

    if (tid < 64) srmin[tid] = ~0ull;
    else if (tid < 128) scmin[tid - 64] = ~0ull;

    {
        int r = tid >> 2, k0 = (tid & 3) * 16;
        const float4* px = (const float4*)(x + (size_t)(i0 + r) * DD + k0);
        const float4* py = (const float4*)(y + (size_t)(j0 + r) * DD + k0);
        #pragma unroll
        for (int q = 0; q < 4; q++) {
            float4 v = px[q];
            xsh[(k0 + q * 4 + 0) * TSTR + r] = v.x;
            xsh[(k0 + q * 4 + 1) * TSTR + r] = v.y;
            xsh[(k0 + q * 4 + 2) * TSTR + r] = v.z;
            xsh[(k0 + q * 4 + 3) * TSTR + r] = v.w;
            float4 u = py[q];
            ysh[(k0 + q * 4 + 0) * TSTR + r] = u.x;
            ysh[(k0 + q * 4 + 1) * TSTR + r] = u.y;
            ysh[(k0 + q * 4 + 2) * TSTR + r] = u.z;
            ysh[(k0 + q * 4 + 3) * TSTR + r] = u.w;
        }
    }
    __syncthreads();

    float acc[4][4];
    #pragma unroll
    for (int a = 0; a < 4; a++)
        #pragma unroll
        for (int b = 0; b < 4; b++) acc[a][b] = 0.0f;

    #pragma unroll
    for (int k = 0; k < DD; k++) {
        float4 xv = *(const float4*)&xsh[k * TSTR + ty * 4];
        float4 yv = *(const float4*)&ysh[k * TSTR + tx * 4];
        float xa[4] = {xv.x, xv.y, xv.z, xv.w};
        float ya[4] = {yv.x, yv.y, yv.z, yv.w};
        #pragma unroll
        for (int a = 0; a < 4; a++)
            #pragma unroll
            for (int b = 0; b < 4; b++)
                acc[a][b] = __fmaf_rn(xa[a], ya[b], acc[a][b]);
    }

    float x2v[4], y2v[4];
    #pragma unroll
    for (int a = 0; a < 4; a++) {
        x2v[a] = g_x2[i0 + ty * 4 + a];
        y2v[a] = g_y2[j0 + tx * 4 + a];
    }
    #pragma unroll
    for (int a = 0; a < 4; a++)
        #pragma unroll
        for (int b = 0; b < 4; b++) {
            float ssum = __fadd_rn(x2v[a], y2v[b]);
            float u    = __fsub_rn(ssum, __fmul_rn(2.0f, acc[a][b]));
            float sq   = fmaxf(u, 0.0f);
            acc[a][b]  = __fsqrt_rn(sq);
        }

    #pragma unroll
    for (int a = 0; a < 4; a++) {
        unsigned long long rk = ~0ull;
        #pragma unroll
        for (int b = 0; b < 4; b++)
            rk = umin64(rk, mkkey(acc[a][b], j0 + tx * 4 + b));
        atomicMin(&srmin[ty * 4 + a], rk);
    }
    #pragma unroll
    for (int b = 0; b < 4; b++) {
        unsigned long long ck = ~0ull;
        #pragma unroll
        for (int a = 0; a < 4; a++)
            ck = umin64(ck, mkkey(acc[a][b], i0 + ty * 4 + a));
        atomicMin(&scmin[tx * 4 + b], ck);
    }

    #pragma unroll
    for (int a = 0; a < 4; a++) {
        float4 o = make_float4(acc[a][0], acc[a][1], acc[a][2], acc[a][3]);
        *(float4*)&g_cost[(size_t)(i0 + ty * 4 + a) * NN + j0 + tx * 4] = o;
    }

    __syncthreads();
    #pragma unroll
    for (int a = 0; a < 4; a++)
        #pragma unroll
        for (int b = 0; b < 4; b++)
            xsh[(tx * 4 + b) * TSTR + ty * 4 + a] = acc[a][b];
    __syncthreads();

    {
        int c = tid >> 2, k0 = (tid & 3) * 16;
        #pragma unroll
        for (int q = 0; q < 4; q++) {
            float4 v = *(const float4*)&xsh[c * TSTR + k0 + q * 4];
            *(float4*)&g_costT[(size_t)(j0 + c) * NN + i0 + k0 + q * 4] = v;
        }
    }

    if (tid < 64) {
        g_rowseg[(size_t)(i0 + tid) * 64 + blockIdx.x] = srmin[tid];
        atomicMin(&g_rowmin[i0 + tid], srmin[tid]);
    } else if (tid < 128) {
        int c = tid - 64;
        g_colseg[(size_t)(j0 + c) * 64 + blockIdx.y] = scmin[c];
        atomicMin(&g_colmin[j0 + c], scmin[c]);
    }
}

// -------------------------------------------------------------------------
// Kernel 3: init match state + barrier counters (every replay).
// -------------------------------------------------------------------------
__global__ void init_kernel() {
    int i = blockIdx.x * blockDim.x + threadIdx.x;
    if (i < NN) {
        g_scol[i] = (unsigned short)(g_rowmin[i] & 0xFFFFu);
        g_crow[i] = (unsigned short)(g_colmin[i] & 0xFFFFu);
    }
    if (i < NN / 32) { g_rowfreeG[i] = ~0u; g_colfreeG[i] = ~0u; }
    if (i == 0) { g_matched = 0; g_bar_cnt = 0; g_bar_gen = 0; }
}

// -------------------------------------------------------------------------
// Kernel 4: persistent multi-SM matcher. 128 co-resident blocks; warp gw
// owns row gw and col gw. Rounds: commit mutual edges -> gridsync -> done?
// -> rescan dead pointers via segment hierarchy -> gridsync.
// Cross-block state read via __ldcg (L2-coherent); seg arrays are
// warp-private by construction (plain access). Exact sorted-greedy result.
// -------------------------------------------------------------------------
__global__ __launch_bounds__(1024, 1)
void pmatch_kernel(float* __restrict__ out) {
    __shared__ int sm_matched;
    int tid = threadIdx.x, lane = tid & 31, w = tid >> 5;
    int gw = blockIdx.x * 32 + w;        // this warp's row AND col index

    while (true) {
        // ---- commit phase: lane 0 of each warp handles row gw
        if (lane == 0) {
            int i = gw;
            if ((__ldcg(&g_rowfreeG[i >> 5]) >> (i & 31)) & 1) {
                int j = __ldcg(&g_scol[i]);
                if ((int)__ldcg(&g_crow[j]) == i) {
                    out[i] = (float)j;
                    atomicAnd(&g_rowfreeG[i >> 5], ~(1u << (i & 31)));
                    atomicAnd(&g_colfreeG[j >> 5], ~(1u << (j & 31)));
                    atomicAdd(&g_matched, 1);
                }
            }
        }
        gridsync();
        if (tid == 0) sm_matched = atomicAdd(&g_matched, 0);
        __syncthreads();
        if (sm_matched == NN) break;

        // ---- rescan phase: warp handles row gw then col gw
        #pragma unroll
        for (int side = 0; side < 2; side++) {
            bool isRow = (side == 0);
            int idx = gw;
            const unsigned int* ofb = isRow ? g_colfreeG : g_rowfreeG;
            const unsigned int* sfb = isRow ? g_rowfreeG : g_colfreeG;
            if (!((__ldcg(&sfb[idx >> 5]) >> (idx & 31)) & 1)) continue;
            int tgt = isRow ? (int)__ldcg(&g_scol[idx]) : (int)__ldcg(&g_crow[idx]);
            if ((__ldcg(&ofb[tgt >> 5]) >> (tgt & 31)) & 1) continue;  // still valid

            unsigned long long* seg = (isRow ? g_rowseg : g_colseg) + (size_t)idx * 64;
            const float* base = (isRow ? g_cost : g_costT) + (size_t)idx * NN;
            unsigned long long best = ~0ull;
            #pragma unroll
            for (int s0 = 0; s0 < 64; s0 += 32) {
                int s = s0 + lane;
                unsigned long long k = seg[s];
                if (k != ~0ull) {
                    int c = (int)(k & 0xFFFFu);
                    if (!((__ldcg(&ofb[c >> 5]) >> (c & 31)) & 1)) {
                        unsigned long long nk = ~0ull;
                        unsigned w0 = __ldcg(&ofb[s * 2]);
                        unsigned w1 = __ldcg(&ofb[s * 2 + 1]);
                        int c0 = s * 64;
                        if (w0 | w1) {
                            const float4* p = (const float4*)(base + c0);
                            #pragma unroll
                            for (int q = 0; q < 16; q++) {
                                unsigned mm = ((q < 8 ? w0 : w1) >> ((q & 7) * 4)) & 0xFu;
                                if (mm) {
                                    float4 v = p[q];
                                    if (mm & 1) nk = umin64(nk, mkkey(v.x, c0 + q * 4 + 0));
                                    if (mm & 2) nk = umin64(nk, mkkey(v.y, c0 + q * 4 + 1));
                                    if (mm & 4) nk = umin64(nk, mkkey(v.z, c0 + q * 4 + 2));
                                    if (mm & 8) nk = umin64(nk, mkkey(v.w, c0 + q * 4 + 3));
                                }
                            }
                        }
                        seg[s] = nk;
                        k = nk;
                    }
                }
                best = umin64(best, k);
            }
            #pragma unroll
            for (int o = 16; o; o >>= 1)
                best = umin64(best, __shfl_down_sync(0xFFFFFFFFu, best, o));
            if (lane == 0) {
                if (isRow) g_scol[idx] = (unsigned short)(best & 0xFFFFu);
                else       g_crow[idx] = (unsigned short)(best & 0xFFFFu);
            }
        }
        gridsync();
    }
}

extern "C" void kernel_launch(void* const* d_in, const int* in_sizes, int n_in,
                              void* d_out, int out_size) {
    const float* x = (const float*)d_in[0];
    const float* y = (const float*)d_in[1];
    float* out = (float*)d_out;

    norms_kernel<<<512, 256>>>(x, y, out);
    cost_kernel<<<dim3(64, 64), 256>>>(x, y);
    init_kernel<<<4, 1024>>>();
    pmatch_kernel<<<NBLK, 1024>>>(out);
}